// round 1
// baseline (speedup 1.0000x reference)
#include <cuda_runtime.h>
#include <cuda_bf16.h>

// SegEncodeLoss: presence-vector BCE over 32x32 tiles of a [32,1024,1024] int32
// label map against preds [32768,19] f32. Output: scalar mean loss (f32).
//
// HBM-bound: 134 MB of targets read once. One CTA per tile, int4 loads,
// warp-OR presence mask, spread-slot double accumulation (avoids
// single-address L2 atomic serialization), tiny init/finalize kernels.

constexpr int Bc = 32, Hc = 1024, Wc = 1024, Gc = 32, Cc = 19;
constexpr int BHc = Hc / Gc;            // 32
constexpr int BWc = Wc / Gc;            // 32
constexpr int NBLK = Bc * BHc * BWc;    // 32768
constexpr int NSLOT = 512;

// 128B-stride accumulator slots -> distinct L2 partitions, parallel atomics.
struct __align__(128) AccSlot { double v; double pad[15]; };
__device__ AccSlot g_acc[NSLOT];

__global__ void seg_init_kernel() {
    int i = blockIdx.x * blockDim.x + threadIdx.x;
    if (i < NSLOT) g_acc[i].v = 0.0;
}

__global__ void __launch_bounds__(256) seg_main_kernel(
    const float* __restrict__ preds,
    const int*   __restrict__ targets)
{
    __shared__ unsigned s_mask;
    const int n   = blockIdx.x;        // tile index, ordered (b, bh, bw)
    const int tid = threadIdx.x;

    if (tid == 0) s_mask = 0u;
    __syncthreads();

    const int b  = n >> 10;            // / (BHc*BWc)
    const int bh = (n >> 5) & 31;
    const int bw = n & 31;

    // Each thread: one int4 (4 labels). 8 threads cover one 128B tile row.
    const int row = tid >> 3;          // 0..31
    const int c4  = tid & 7;           // 0..7
    const int4* p = reinterpret_cast<const int4*>(
        targets + (size_t)b * Hc * Wc + (size_t)(bh * Gc + row) * Wc + bw * Gc) + c4;
    const int4 v = __ldg(p);

    // Labels are in [0,19); 19 bits fit a u32.
    unsigned m = (1u << v.x) | (1u << v.y) | (1u << v.z) | (1u << v.w);
    m = __reduce_or_sync(0xffffffffu, m);
    if ((tid & 31) == 0) atomicOr(&s_mask, m);
    __syncthreads();

    // First warp: 19 BCE-with-logits terms, warp-sum, one spread-slot atomic.
    if (tid < 32) {
        const unsigned mask = s_mask;
        float loss = 0.0f;
        if (tid < Cc) {
            const float x = preds[n * Cc + tid];
            const float t = ((mask >> tid) & 1u) ? 1.0f : 0.0f;
            // BCE-with-logits, stable: max(x,0) - x*t + log1p(exp(-|x|))
            loss = fmaxf(x, 0.0f) - x * t + log1pf(__expf(-fabsf(x)));
        }
        #pragma unroll
        for (int o = 16; o > 0; o >>= 1)
            loss += __shfl_down_sync(0xffffffffu, loss, o);
        if (tid == 0)
            atomicAdd(&g_acc[n & (NSLOT - 1)].v, (double)loss);
    }
}

__global__ void __launch_bounds__(256) seg_finalize_kernel(float* __restrict__ out) {
    __shared__ double sh[8];
    double s = 0.0;
    for (int i = threadIdx.x; i < NSLOT; i += 256) s += g_acc[i].v;
    #pragma unroll
    for (int o = 16; o > 0; o >>= 1)
        s += __shfl_down_sync(0xffffffffu, s, o);
    if ((threadIdx.x & 31) == 0) sh[threadIdx.x >> 5] = s;
    __syncthreads();
    if (threadIdx.x < 8) {
        double t = sh[threadIdx.x];
        #pragma unroll
        for (int o = 4; o > 0; o >>= 1)
            t += __shfl_down_sync(0x000000ffu, t, o);
        if (threadIdx.x == 0)
            out[0] = (float)(t / ((double)NBLK * (double)Cc));
    }
}

extern "C" void kernel_launch(void* const* d_in, const int* in_sizes, int n_in,
                              void* d_out, int out_size) {
    const float* preds   = (const float*)d_in[0];
    const int*   targets = (const int*)d_in[1];
    float*       out     = (float*)d_out;

    seg_init_kernel<<<1, NSLOT>>>();
    seg_main_kernel<<<NBLK, 256>>>(preds, targets);
    seg_finalize_kernel<<<1, 256>>>(out);
}

// round 2
// speedup vs baseline: 1.3957x; 1.3957x over previous
#include <cuda_runtime.h>
#include <cuda_bf16.h>

// SegEncodeLoss fused single kernel.
// targets [32,1024,1024] i32 -> per 32x32 tile 19-class presence mask ->
// BCE-with-logits vs preds [32768,19] f32 -> scalar mean (f32).
//
// HBM-bound (134 MB read once). 8 tiles per CTA, one warp per tile,
// 8 front-batched int4 loads per thread (MLP=8). Warp-OR gives the full
// tile mask with no shared/global atomics. Last-CTA reduction via
// self-resetting atomicInc counter (graph-replay safe, no init kernel).

constexpr int Hc = 1024, Wc = 1024, Cc = 19;
constexpr int NBLK = 32 * 32 * 32;            // 32768 tiles
constexpr int TPC  = 8;                       // tiles per CTA (1 warp each)
constexpr int NCTA = NBLK / TPC;              // 4096

__device__ float    g_part[NCTA];
__device__ unsigned g_count = 0;              // wraps to 0 via atomicInc limit

__global__ void __launch_bounds__(256) seg_fused_kernel(
    const float* __restrict__ preds,
    const int*   __restrict__ targets,
    float*       __restrict__ out)
{
    const int tid  = threadIdx.x;
    const int warp = tid >> 5;                // 0..7 -> tile within CTA
    const int lane = tid & 31;

    const int n  = blockIdx.x * TPC + warp;   // global tile id
    const int b  = n >> 10;
    const int bh = (n >> 5) & 31;
    const int bw = n & 31;

    // Tile base as int4 index. Row stride = 1024 ints = 256 int4.
    const int rb = lane >> 3;                 // 0..3
    const int c4 = lane & 7;                  // 0..7
    const int4* base = reinterpret_cast<const int4*>(targets)
                     + (size_t)b * (Hc * Wc / 4)
                     + (size_t)(bh * 32 + rb) * (Wc / 4)
                     + bw * 8 + c4;

    // 8 independent 16B loads (rows rb, rb+4, ..., rb+28): MLP=8, front-batched.
    int4 v[8];
    #pragma unroll
    for (int i = 0; i < 8; i++)
        v[i] = __ldg(base + i * 4 * (Wc / 4));

    unsigned m = 0;
    #pragma unroll
    for (int i = 0; i < 8; i++)
        m |= (1u << v[i].x) | (1u << v[i].y) | (1u << v[i].z) | (1u << v[i].w);
    m = __reduce_or_sync(0xffffffffu, m);     // full 32x32 tile mask, all lanes

    // BCE-with-logits for this tile's 19 classes (lanes 0..18).
    float loss = 0.0f;
    if (lane < Cc) {
        const float x = preds[n * Cc + lane];
        const float t = ((m >> lane) & 1u) ? 1.0f : 0.0f;
        loss = fmaxf(x, 0.0f) - x * t + log1pf(__expf(-fabsf(x)));
    }
    #pragma unroll
    for (int o = 16; o > 0; o >>= 1)
        loss += __shfl_down_sync(0xffffffffu, loss, o);

    __shared__ float s_part[TPC];
    __shared__ bool  s_last;
    if (lane == 0) s_part[warp] = loss;
    __syncthreads();

    if (tid == 0) {
        float cs = 0.0f;
        #pragma unroll
        for (int i = 0; i < TPC; i++) cs += s_part[i];
        g_part[blockIdx.x] = cs;
        __threadfence();
        // Self-resetting: the CTA seeing old == NCTA-1 is last; counter -> 0.
        unsigned old = atomicInc(&g_count, NCTA - 1u);
        s_last = (old == NCTA - 1u);
    }
    __syncthreads();

    if (s_last) {
        // Final reduction over 4096 partials (hot in L2).
        double s = 0.0;
        for (int i = tid; i < NCTA; i += 256)
            s += (double)__ldcg(&g_part[i]);
        #pragma unroll
        for (int o = 16; o > 0; o >>= 1)
            s += __shfl_down_sync(0xffffffffu, s, o);
        __shared__ double sh[8];
        if (lane == 0) sh[warp] = s;
        __syncthreads();
        if (tid < 8) {
            double t2 = sh[tid];
            #pragma unroll
            for (int o = 4; o > 0; o >>= 1)
                t2 += __shfl_down_sync(0x000000ffu, t2, o);
            if (tid == 0)
                out[0] = (float)(t2 / ((double)NBLK * (double)Cc));
        }
    }
}

extern "C" void kernel_launch(void* const* d_in, const int* in_sizes, int n_in,
                              void* d_out, int out_size) {
    const float* preds   = (const float*)d_in[0];
    const int*   targets = (const int*)d_in[1];
    float*       out     = (float*)d_out;

    seg_fused_kernel<<<NCTA, 256>>>(preds, targets, out);
}